// round 10
// baseline (speedup 1.0000x reference)
#include <cuda_runtime.h>
#include <cstdint>

#define BATCH 8
#define NPIX (1 << 20)
#define HARD_IND 524288u
#define PSOFT (104857.0 / 1048576.0)
#define TOTAL_ELEMS 25165824.0

// ---------------- scratch (static device memory; zero-initialized at load) -------
// INVARIANT: every consumer resets its cross-run accumulator after use.
__device__ float              g_res[BATCH * NPIX];   // 32 MB (fully rewritten)
__device__ unsigned           g_hist1[BATCH][4096];  // zeroed by k_sel1 after read
__device__ unsigned long long g_hist2[BATCH][1024];  // {cnt<<40 | sum_low10}; zeroed by k_final
__device__ double             g_sumAll[BATCH];       // zeroed by k_final after read
__device__ double             g_hardHigh[BATCH];     // zeroed by k_final after read
__device__ int                g_cand[BATCH];
__device__ unsigned           g_above[BATCH];
__device__ double             g_total;               // zeroed by last k_final block
__device__ unsigned           g_done;                // completion ticket, self-reset

// ---------------- K1: res = sum_c |x-y| + hist1 + total sum ----------------------
// DRAM-bound (224 MB) -> the extra sum FADDs are free here.
__global__ void __launch_bounds__(256) k_res(const float* __restrict__ x,
                                             const float* __restrict__ y) {
    __shared__ unsigned sh[4096];
    __shared__ double wall[8];
    for (int i = threadIdx.x; i < 4096; i += 256) sh[i] = 0;
    __syncthreads();

    const int blocksPerBatch = NPIX / 4096;   // 256
    int b   = blockIdx.x / blocksPerBatch;
    int blk = blockIdx.x % blocksPerBatch;
    const float* xb = x + (size_t)b * 3 * NPIX;
    const float* yb = y + (size_t)b * 3 * NPIX;
    float* rb = g_res + (size_t)b * NPIX;
    int pix0 = blk * 4096;
    int lane = threadIdx.x & 31;
    float fs = 0.0f;

#pragma unroll
    for (int it = 0; it < 4; ++it) {
        int i = pix0 + it * 1024 + threadIdx.x * 4;
        float4 a0 = *(const float4*)(xb + i);
        float4 b0 = *(const float4*)(yb + i);
        float4 a1 = *(const float4*)(xb + NPIX + i);
        float4 b1 = *(const float4*)(yb + NPIX + i);
        float4 a2 = *(const float4*)(xb + 2 * NPIX + i);
        float4 b2 = *(const float4*)(yb + 2 * NPIX + i);
        float4 r;
        r.x = (fabsf(a0.x - b0.x) + fabsf(a1.x - b1.x)) + fabsf(a2.x - b2.x);
        r.y = (fabsf(a0.y - b0.y) + fabsf(a1.y - b1.y)) + fabsf(a2.y - b2.y);
        r.z = (fabsf(a0.z - b0.z) + fabsf(a1.z - b1.z)) + fabsf(a2.z - b2.z);
        r.w = (fabsf(a0.w - b0.w) + fabsf(a1.w - b1.w)) + fabsf(a2.w - b2.w);
        *(float4*)(rb + i) = r;
        atomicAdd(&sh[__float_as_uint(r.x) >> 20], 1u);
        atomicAdd(&sh[__float_as_uint(r.y) >> 20], 1u);
        atomicAdd(&sh[__float_as_uint(r.z) >> 20], 1u);
        atomicAdd(&sh[__float_as_uint(r.w) >> 20], 1u);
        fs += ((r.x + r.y) + (r.z + r.w));
    }
    for (int o = 16; o; o >>= 1) fs += __shfl_down_sync(0xffffffffu, fs, o);
    int w = threadIdx.x >> 5;
    if (!lane) wall[w] = (double)fs;
    __syncthreads();
    if (threadIdx.x == 0) {
        double sa = 0.0;
        for (int i = 0; i < 8; ++i) sa += wall[i];
        atomicAdd(&g_sumAll[b], sa);
    }
    for (int i = threadIdx.x; i < 4096; i += 256) {
        unsigned c = sh[i];
        if (c) atomicAdd(&g_hist1[b][i], c);
    }
}

// ---------------- K2: candidate level-1 bin (rank HARD_IND, descending) -----------
__global__ void __launch_bounds__(1024) k_sel1() {
    int b = blockIdx.x, tid = threadIdx.x, lane = tid & 31, w = tid >> 5;
    __shared__ unsigned sh[4096];
    for (int i = tid; i < 4096; i += 1024) {
        sh[i] = g_hist1[b][i];
        g_hist1[b][i] = 0;                    // reset for next run
    }
    __syncthreads();
    unsigned v = sh[4 * tid] + sh[4 * tid + 1] + sh[4 * tid + 2] + sh[4 * tid + 3];
    unsigned s = v;
    for (int o = 1; o < 32; o <<= 1) {
        unsigned t = __shfl_down_sync(0xffffffffu, s, o);
        if (lane + o < 32) s += t;
    }
    __shared__ unsigned wtot[32];
    if (!lane) wtot[w] = s;
    __syncthreads();
    unsigned above = 0;
    for (int u = w + 1; u < 32; ++u) above += wtot[u];
    unsigned suffExcl = above + s - v;
    if (suffExcl <= HARD_IND && HARD_IND < suffExcl + v) {
        unsigned cum = suffExcl;
        for (int j = 3; j >= 0; --j) {
            unsigned c = sh[4 * tid + j];
            if (cum + c > HARD_IND) { g_cand[b] = 4 * tid + j; g_above[b] = cum; break; }
            cum += c;
        }
    }
}

// ---------------- K3: hard-high sum + packed level-2 histogram (lean loop) --------
__global__ void __launch_bounds__(256) k_refine() {
    const int blocksPerBatch = NPIX / 4096;
    int b   = blockIdx.x / blocksPerBatch;
    int blk = blockIdx.x % blocksPerBatch;
    unsigned candLo = (unsigned)g_cand[b] << 20;
    unsigned candHi = candLo + (1u << 20);
    const float* rb = g_res + (size_t)b * NPIX;
    int pix0 = blk * 4096;
    int lane = threadIdx.x & 31;

    __shared__ unsigned long long sh2[1024];  // {cnt<<40 | sum_low10} per sub-bin
    __shared__ double whigh[8];
    for (int i = threadIdx.x; i < 1024; i += 256) sh2[i] = 0ull;
    __syncthreads();

    float fh = 0.0f;
#pragma unroll
    for (int it = 0; it < 4; ++it) {
        int i = pix0 + it * 1024 + threadIdx.x * 4;
        float4 r = *(const float4*)(rb + i);
        float vv[4] = {r.x, r.y, r.z, r.w};
#pragma unroll
        for (int k = 0; k < 4; ++k) {
            float v = vv[k];
            unsigned bits = __float_as_uint(v);
            if (bits >= candHi) fh += v;            // raw-bit compare, no shift
            else if (bits - candLo < (1u << 20))    // candidate bin (rare)
                atomicAdd(&sh2[(bits >> 10) & 1023u],
                          (1ull << 40) | (unsigned long long)(bits & 1023u));
        }
    }
    for (int o = 16; o; o >>= 1) fh += __shfl_down_sync(0xffffffffu, fh, o);
    int w = threadIdx.x >> 5;
    if (!lane) whigh[w] = (double)fh;
    __syncthreads();
    if (threadIdx.x == 0) {
        double sh_ = 0.0;
        for (int i = 0; i < 8; ++i) sh_ += whigh[i];
        atomicAdd(&g_hardHigh[b], sh_);
    }
    __syncthreads();
    // flush only nonzero level-2 bins (~25 per block) — spread over 1024 addrs
    for (int i = threadIdx.x; i < 1024; i += 256) {
        unsigned long long h = sh2[i];
        if (h) atomicAdd(&g_hist2[b][i], h);
    }
}

// ---------------- helper: count strictly above tid (descending suffix) ------------
__device__ __forceinline__ unsigned suff_excl(unsigned v, int tid, unsigned* wtot) {
    int lane = tid & 31, w = tid >> 5;
    unsigned s = v;
    for (int o = 1; o < 32; o <<= 1) {
        unsigned t = __shfl_down_sync(0xffffffffu, s, o);
        if (lane + o < 32) s += t;
    }
    __syncthreads();
    if (!lane) wtot[w] = s;
    __syncthreads();
    unsigned above = 0;
    for (int u = w + 1; u < 32; ++u) above += wtot[u];
    return above + s - v;
}

// ---------------- K4: per-batch result + last-block writes output -----------------
// Within-sub-bin rank resolved by the sub-bin MEAN (exact cnt + exact low-bit sum);
// sub-bin width ~2.4e-4 x ~47 elems -> rel impact ~5e-9.
__global__ void __launch_bounds__(1024) k_final(float* __restrict__ out) {
    int b = blockIdx.x, tid = threadIdx.x, lane = tid & 31, w = tid >> 5;
    __shared__ unsigned wtot[32];
    __shared__ double   wshd[32];
    __shared__ int sC2;
    __shared__ unsigned sRin2;
    __shared__ double sC2sum; __shared__ unsigned sC2cnt;

    unsigned cand = (unsigned)g_cand[b];

    unsigned long long h = g_hist2[b][tid];
    g_hist2[b][tid] = 0ull;                   // reset for next run (same thread)
    unsigned cnt   = (unsigned)(h >> 40);
    double sumlow  = (double)(h & 0xFFFFFFFFFFull);
    double base    = (double)__uint_as_float((cand << 20) | ((unsigned)tid << 10));
    double ulp     = (double)__uint_as_float((cand << 20) | 1u)
                   - (double)__uint_as_float(cand << 20);   // exact
    double binsum  = (double)cnt * base + sumlow * ulp;     // exact sub-bin sum

    unsigned se  = suff_excl(cnt, tid, wtot);
    unsigned rin = HARD_IND - g_above[b];
    if (se <= rin && rin < se + cnt) { sC2 = tid; sRin2 = rin - se; }
    __syncthreads();
    int c2 = sC2;
    if (tid == c2) { sC2sum = binsum; sC2cnt = cnt; }

    double sa = (tid > c2) ? binsum : 0.0;
    for (int o = 16; o; o >>= 1) sa += __shfl_down_sync(0xffffffffu, sa, o);
    if (!lane) wshd[w] = sa;
    __syncthreads();
    if (tid == 0) {
        double s = 0.0;
        for (int i = 0; i < 32; ++i) s += wshd[i];
        double meanC2 = sC2sum / (double)sC2cnt;
        double within = (double)sRin2 * meanC2;   // top-rin2 elems ~ sub-bin mean
        double hardSum = g_hardHigh[b] + s + within;
        double result  = hardSum + PSOFT * (g_sumAll[b] - hardSum);
        atomicAdd(&g_total, result);
        g_hardHigh[b] = 0.0;                  // reset for next run
        g_sumAll[b]  = 0.0;
        __threadfence();
        unsigned ticket = atomicAdd(&g_done, 1u);
        if (ticket == BATCH - 1) {            // last block: emit scalar + reset
            out[0] = (float)(g_total / TOTAL_ELEMS);
            g_total = 0.0;
            g_done  = 0u;
        }
    }
}

extern "C" void kernel_launch(void* const* d_in, const int* in_sizes, int n_in,
                              void* d_out, int out_size) {
    const float* x = (const float*)d_in[0];
    const float* y = (const float*)d_in[1];
    float* out = (float*)d_out;
    k_res   <<<2048, 256>>>(x, y);
    k_sel1  <<<BATCH, 1024>>>();
    k_refine<<<2048, 256>>>();
    k_final <<<BATCH, 1024>>>(out);
}